// round 3
// baseline (speedup 1.0000x reference)
#include <cuda_runtime.h>
#include <cuda_bf16.h>
#include <math.h>

// Problem constants (fixed by the benchmark)
#define BB 2
#define SS 2048
#define EE 1024
#define HH 16
#define DD 64
#define MM (BB * SS)          // 4096 rows for projections
#define SCALE 0.03125f        // 1/sqrt(1024)

// -------- scratch (static device globals; no allocation allowed) --------
__device__ float g_Q[MM * EE];
__device__ float g_K[MM * EE];
__device__ float g_V[MM * EE];
__device__ float g_A[MM * EE];

// ============================================================
// SGEMM: C[M,N] = A[M,K] @ W[K,N] + bias[N]
// BM=BN=128, BK=8, 256 threads, 8x8 per-thread microtile
// ============================================================
__global__ __launch_bounds__(256) void sgemm_bias_kernel(
    const float* __restrict__ A, const float* __restrict__ W,
    const float* __restrict__ bias, float* __restrict__ C,
    int M, int N, int K)
{
    constexpr int BM = 128, BN = 128, BK = 8;
    __shared__ float As[BK][BM];   // transposed A tile
    __shared__ float Bs[BK][BN];

    const int tid = threadIdx.x;
    const int bx = blockIdx.x;     // N tile
    const int by = blockIdx.y;     // M tile
    const int tx = tid & 15;
    const int ty = tid >> 4;

    // global-load mapping
    const int a_row = tid >> 1;          // 0..127
    const int a_col = (tid & 1) * 4;     // 0 or 4
    const int b_row = tid >> 5;          // 0..7
    const int b_col = (tid & 31) * 4;    // 0..124

    const float* Ab = A + (size_t)(by * BM + a_row) * K + a_col;
    const float* Bb = W + (size_t)b_row * N + bx * BN + b_col;

    float acc[8][8];
    #pragma unroll
    for (int i = 0; i < 8; i++)
        #pragma unroll
        for (int j = 0; j < 8; j++) acc[i][j] = 0.f;

    for (int k0 = 0; k0 < K; k0 += BK) {
        float4 av = *(const float4*)(Ab + k0);
        float4 bv = *(const float4*)(Bb + (size_t)k0 * N);
        __syncthreads();
        As[a_col + 0][a_row] = av.x;
        As[a_col + 1][a_row] = av.y;
        As[a_col + 2][a_row] = av.z;
        As[a_col + 3][a_row] = av.w;
        *(float4*)&Bs[b_row][b_col] = bv;
        __syncthreads();

        #pragma unroll
        for (int kk = 0; kk < BK; kk++) {
            float a_f[8], b_f[8];
            *(float4*)&a_f[0] = *(const float4*)&As[kk][ty * 4];
            *(float4*)&a_f[4] = *(const float4*)&As[kk][ty * 4 + 64];
            *(float4*)&b_f[0] = *(const float4*)&Bs[kk][tx * 4];
            *(float4*)&b_f[4] = *(const float4*)&Bs[kk][tx * 4 + 64];
            #pragma unroll
            for (int i = 0; i < 8; i++)
                #pragma unroll
                for (int j = 0; j < 8; j++)
                    acc[i][j] += a_f[i] * b_f[j];
        }
    }

    // bias
    float bsum[8];
    #pragma unroll
    for (int j = 0; j < 4; j++) {
        bsum[j]     = bias[bx * BN + tx * 4 + j];
        bsum[4 + j] = bias[bx * BN + tx * 4 + 64 + j];
    }

    #pragma unroll
    for (int i = 0; i < 8; i++) {
        int r = by * BM + ty * 4 + (i & 3) + (i >> 2) * 64;
        float* Cp = C + (size_t)r * N + bx * BN + tx * 4;
        float4 c0, c1;
        c0.x = acc[i][0] + bsum[0]; c0.y = acc[i][1] + bsum[1];
        c0.z = acc[i][2] + bsum[2]; c0.w = acc[i][3] + bsum[3];
        c1.x = acc[i][4] + bsum[4]; c1.y = acc[i][5] + bsum[5];
        c1.z = acc[i][6] + bsum[6]; c1.w = acc[i][7] + bsum[7];
        *(float4*)Cp = c0;
        *(float4*)(Cp + 64) = c1;
    }
}

// ============================================================
// Flash attention (causal), fp32.
// Layouts: Q,K,V,O all [B, S, E] with head h occupying cols h*64..h*64+63.
// Block: 128 threads = 128 q-rows. Grid: (S/128, H, B).
// Each thread owns one q-row fully: q[64] and o[64] in registers,
// scores staged in padded smem (row-private), no cross-thread reductions.
// ============================================================
#define KV_STRIDE 68          // 64 + 4 pad; 68*4 = 272 B = 16B-aligned rows
#define SS_STRIDE 65          // odd pad -> conflict-free column access
#define ATTN_SMEM_BYTES ((2 * 64 * KV_STRIDE + 128 * SS_STRIDE) * 4)

__global__ __launch_bounds__(128, 1) void attn_kernel(
    const float* __restrict__ Q, const float* __restrict__ K,
    const float* __restrict__ V, float* __restrict__ O)
{
    extern __shared__ float smem[];
    float* Ks = smem;                    // [64][KV_STRIDE]
    float* Vs = smem + 64 * KV_STRIDE;   // [64][KV_STRIDE]
    float* Sc = smem + 2 * 64 * KV_STRIDE; // [128][SS_STRIDE]

    const int tid = threadIdx.x;
    const int q0 = blockIdx.x * 128;
    const int h  = blockIdx.y;
    const int b  = blockIdx.z;

    const float* Qb = Q + ((size_t)b * SS) * EE + h * DD;
    const float* Kb = K + ((size_t)b * SS) * EE + h * DD;
    const float* Vb = V + ((size_t)b * SS) * EE + h * DD;
    float*       Ob = O + ((size_t)b * SS) * EE + h * DD;

    // stage Q tile (coalesced), then pull own row into registers
    for (int idx = tid; idx < 128 * 64; idx += 128) {
        int r = idx >> 6, d = idx & 63;
        Sc[r * SS_STRIDE + d] = Qb[(size_t)(q0 + r) * EE + d];
    }
    __syncthreads();

    float q[64];
    #pragma unroll
    for (int d = 0; d < 64; d++) q[d] = Sc[tid * SS_STRIDE + d];

    float o[64];
    #pragma unroll
    for (int d = 0; d < 64; d++) o[d] = 0.f;
    float m = -INFINITY, l = 0.f;

    const int grow   = q0 + tid;
    const int ktiles = q0 / 64 + 2;   // covers kv rows 0 .. q0+127

    for (int kt = 0; kt < ktiles; kt++) {
        __syncthreads();
        // load K/V tiles (coalesced: 64 contiguous floats per row)
        for (int idx = tid; idx < 64 * 64; idx += 128) {
            int r = idx >> 6, d = idx & 63;
            size_t g = (size_t)(kt * 64 + r) * EE + d;
            Ks[r * KV_STRIDE + d] = Kb[g];
            Vs[r * KV_STRIDE + d] = Vb[g];
        }
        __syncthreads();

        int jmax = grow - kt * 64;
        if (jmax >= 0) {
            if (jmax > 63) jmax = 63;
            float mnew = m;
            // pass 1: scores + running max
            for (int j = 0; j <= jmax; j++) {
                const float4* kr = (const float4*)(Ks + j * KV_STRIDE);
                float s = 0.f;
                #pragma unroll
                for (int d4 = 0; d4 < 16; d4++) {
                    float4 kv = kr[d4];
                    s += q[4 * d4 + 0] * kv.x + q[4 * d4 + 1] * kv.y
                       + q[4 * d4 + 2] * kv.z + q[4 * d4 + 3] * kv.w;
                }
                s *= SCALE;
                Sc[tid * SS_STRIDE + j] = s;
                mnew = fmaxf(mnew, s);
            }
            // rescale running state (first tile: m=-inf -> corr=0, state was 0)
            float corr = __expf(m - mnew);
            l *= corr;
            #pragma unroll
            for (int d = 0; d < 64; d++) o[d] *= corr;
            // pass 2: p = exp(s - mnew); accumulate PV
            for (int j = 0; j <= jmax; j++) {
                float p = __expf(Sc[tid * SS_STRIDE + j] - mnew);
                l += p;
                const float4* vr = (const float4*)(Vs + j * KV_STRIDE);
                #pragma unroll
                for (int d4 = 0; d4 < 16; d4++) {
                    float4 vv = vr[d4];
                    o[4 * d4 + 0] += p * vv.x;
                    o[4 * d4 + 1] += p * vv.y;
                    o[4 * d4 + 2] += p * vv.z;
                    o[4 * d4 + 3] += p * vv.w;
                }
            }
            m = mnew;
        }
    }

    // normalize, stage to smem, store coalesced
    __syncthreads();
    float inv = 1.0f / l;
    #pragma unroll
    for (int d = 0; d < 64; d++) Sc[tid * SS_STRIDE + d] = o[d] * inv;
    __syncthreads();
    for (int idx = tid; idx < 128 * 64; idx += 128) {
        int r = idx >> 6, d = idx & 63;
        Ob[(size_t)(q0 + r) * EE + d] = Sc[r * SS_STRIDE + d];
    }
}

// ============================================================
// Host launcher
// ============================================================
extern "C" void kernel_launch(void* const* d_in, const int* in_sizes, int n_in,
                              void* d_out, int out_size)
{
    (void)in_sizes; (void)n_in; (void)out_size;
    const float* x  = (const float*)d_in[0];
    const float* Wq = (const float*)d_in[1];
    const float* bq = (const float*)d_in[2];
    const float* Wk = (const float*)d_in[3];
    const float* bk = (const float*)d_in[4];
    const float* Wv = (const float*)d_in[5];
    const float* bv = (const float*)d_in[6];
    const float* Wo = (const float*)d_in[7];
    const float* bo = (const float*)d_in[8];
    float* out = (float*)d_out;

    float *Qp, *Kp, *Vp, *Ap;
    cudaGetSymbolAddress((void**)&Qp, g_Q);
    cudaGetSymbolAddress((void**)&Kp, g_K);
    cudaGetSymbolAddress((void**)&Vp, g_V);
    cudaGetSymbolAddress((void**)&Ap, g_A);

    cudaFuncSetAttribute(attn_kernel,
                         cudaFuncAttributeMaxDynamicSharedMemorySize,
                         ATTN_SMEM_BYTES);

    dim3 gg(EE / 128, MM / 128);   // (8, 32)
    sgemm_bias_kernel<<<gg, 256>>>(x, Wq, bq, Qp, MM, EE, EE);
    sgemm_bias_kernel<<<gg, 256>>>(x, Wk, bk, Kp, MM, EE, EE);
    sgemm_bias_kernel<<<gg, 256>>>(x, Wv, bv, Vp, MM, EE, EE);

    dim3 ga(SS / 128, HH, BB);     // (16, 16, 2)
    attn_kernel<<<ga, 128, ATTN_SMEM_BYTES>>>(Qp, Kp, Vp, Ap);

    sgemm_bias_kernel<<<gg, 256>>>(Ap, Wo, bo, out, MM, EE, EE);
}

// round 4
// speedup vs baseline: 1.2743x; 1.2743x over previous
#include <cuda_runtime.h>
#include <cuda_bf16.h>
#include <math.h>
#include <stdint.h>

// Problem constants (fixed by the benchmark)
#define BB 2
#define SS 2048
#define EE 1024
#define HH 16
#define DD 64
#define MM (BB * SS)          // 4096 rows for projections
#define SCALE 0.03125f        // 1/sqrt(1024)

#define GEMM_K 3072           // 3*EE (bf16x3 emulation folded into K)
#define GEMM_N 1024

// -------- scratch (static device globals; no allocation allowed) --------
__device__ float g_Q[MM * EE];
__device__ float g_K[MM * EE];
__device__ float g_V[MM * EE];
__device__ float g_A[MM * EE];
__device__ __nv_bfloat16 g_A3[(size_t)MM * GEMM_K];        // [M, 3K]  (hi|hi|lo)
__device__ __nv_bfloat16 g_B3[4][(size_t)GEMM_K * GEMM_N]; // [3K, N]  (hi;lo;hi)

__device__ __forceinline__ uint32_t sptr(const void* p) {
    return (uint32_t)__cvta_generic_to_shared(p);
}

// ============================================================
// Split kernels: fp32 -> (hi, lo) bf16 pair layouts
// x = hi + lo with |residual| ~ 2^-17 |x|
// ============================================================
__global__ void split_a3_kernel(const float* __restrict__ X,
                                __nv_bfloat16* __restrict__ A3)
{
    int idx = blockIdx.x * 256 + threadIdx.x;           // over MM*EE
    if (idx >= MM * EE) return;
    int r = idx >> 10, k = idx & 1023;
    float x = X[idx];
    __nv_bfloat16 hi = __float2bfloat16(x);
    __nv_bfloat16 lo = __float2bfloat16(x - __bfloat162float(hi));
    size_t base = (size_t)r * GEMM_K;
    A3[base + k]        = hi;
    A3[base + 1024 + k] = hi;
    A3[base + 2048 + k] = lo;
}

__global__ void split_b3_kernel(const float* __restrict__ W,
                                __nv_bfloat16* __restrict__ B3)
{
    int idx = blockIdx.x * 256 + threadIdx.x;           // over EE*EE
    if (idx >= EE * EE) return;
    float w = W[idx];
    __nv_bfloat16 hi = __float2bfloat16(w);
    __nv_bfloat16 lo = __float2bfloat16(w - __bfloat162float(hi));
    B3[idx]                    = hi;   // rows [0,1024)    : Bhi (pairs Ahi)
    B3[idx + 1024 * 1024]      = lo;   // rows [1024,2048) : Blo (pairs Ahi)
    B3[idx + 2048 * 1024]      = hi;   // rows [2048,3072) : Bhi (pairs Alo)
}

// ============================================================
// bf16x3 GEMM via mma.sync.m16n8k16 (HMMA), fp32 accumulate.
// C[M,1024] = A3[M,3072] @ B3[3072,1024] + bias
// Block 128x128, BK=32, 256 threads (8 warps, 4m x 2n), cp.async
// double buffered, ldmatrix with conflict-free padded strides.
// ============================================================
__global__ __launch_bounds__(256, 2) void gemm_bf16x3_kernel(
    const __nv_bfloat16* __restrict__ A,
    const __nv_bfloat16* __restrict__ B,
    const float* __restrict__ bias,
    float* __restrict__ C)
{
    constexpr int BM = 128, BN = 128, BK = 32;
    constexpr int AST = 40;    // A smem row stride (bf16): 80B, LDSM conflict-free
    constexpr int BST = 136;   // B smem row stride (bf16): 272B, LDSM conflict-free

    __shared__ __align__(16) __nv_bfloat16 As[2][BM * AST];
    __shared__ __align__(16) __nv_bfloat16 Bs[2][BK * BST];

    const int tid  = threadIdx.x;
    const int lane = tid & 31;
    const int warp = tid >> 5;
    const int bm = blockIdx.y * BM;
    const int bn = blockIdx.x * BN;
    const int wm = (warp >> 1) * 32;   // warp m-offset within tile
    const int wn = (warp & 1) * 64;    // warp n-offset within tile

    float acc[2][8][4];
    #pragma unroll
    for (int i = 0; i < 2; i++)
        #pragma unroll
        for (int j = 0; j < 8; j++)
            #pragma unroll
            for (int k = 0; k < 4; k++) acc[i][j][k] = 0.f;

    // global->smem chunk mapping (16B chunks, 2 A-chunks + 2 B-chunks / thread)
    const int ar0 = tid >> 2,        ak0 = (tid & 3) * 8;
    const int ar1 = (tid + 256) >> 2, ak1 = (tid & 3) * 8;   // (tid+256)&3 == tid&3
    const int br0 = tid >> 4,        bn0 = (tid & 15) * 8;
    const int br1 = (tid + 256) >> 4, bn1 = (tid & 15) * 8;

    #define LOAD_STAGE(buf, k0)                                                              \
        do {                                                                                 \
            asm volatile("cp.async.cg.shared.global [%0], [%1], 16;" ::                      \
                "r"(sptr(&As[buf][ar0 * AST + ak0])),                                        \
                "l"(A + (size_t)(bm + ar0) * GEMM_K + (k0) + ak0));                          \
            asm volatile("cp.async.cg.shared.global [%0], [%1], 16;" ::                      \
                "r"(sptr(&As[buf][ar1 * AST + ak1])),                                        \
                "l"(A + (size_t)(bm + ar1) * GEMM_K + (k0) + ak1));                          \
            asm volatile("cp.async.cg.shared.global [%0], [%1], 16;" ::                      \
                "r"(sptr(&Bs[buf][br0 * BST + bn0])),                                        \
                "l"(B + (size_t)((k0) + br0) * GEMM_N + bn + bn0));                          \
            asm volatile("cp.async.cg.shared.global [%0], [%1], 16;" ::                      \
                "r"(sptr(&Bs[buf][br1 * BST + bn1])),                                        \
                "l"(B + (size_t)((k0) + br1) * GEMM_N + bn + bn1));                          \
        } while (0)

    LOAD_STAGE(0, 0);
    asm volatile("cp.async.commit_group;");

    constexpr int NSTEPS = GEMM_K / BK;   // 96
    int buf = 0;

    for (int it = 0; it < NSTEPS; it++) {
        if (it + 1 < NSTEPS) {
            LOAD_STAGE(buf ^ 1, (it + 1) * BK);
            asm volatile("cp.async.commit_group;");
            asm volatile("cp.async.wait_group 1;");
        } else {
            asm volatile("cp.async.wait_group 0;");
        }
        __syncthreads();

        #pragma unroll
        for (int ks = 0; ks < 2; ks++) {
            const int k0 = ks * 16;
            uint32_t af[2][4];
            #pragma unroll
            for (int mi = 0; mi < 2; mi++) {
                uint32_t addr = sptr(&As[buf][(wm + mi * 16 + (lane & 15)) * AST
                                              + k0 + (lane >> 4) * 8]);
                asm volatile("ldmatrix.sync.aligned.m8n8.x4.shared.b16 {%0,%1,%2,%3}, [%4];"
                    : "=r"(af[mi][0]), "=r"(af[mi][1]), "=r"(af[mi][2]), "=r"(af[mi][3])
                    : "r"(addr));
            }
            uint32_t bf0[8], bf1[8];
            #pragma unroll
            for (int ng = 0; ng < 4; ng++) {
                uint32_t addr = sptr(&Bs[buf][(k0 + (lane & 15)) * BST
                                              + wn + ng * 16 + (lane >> 4) * 8]);
                uint32_t r0, r1, r2, r3;
                asm volatile("ldmatrix.sync.aligned.m8n8.x4.trans.shared.b16 {%0,%1,%2,%3}, [%4];"
                    : "=r"(r0), "=r"(r1), "=r"(r2), "=r"(r3) : "r"(addr));
                bf0[2 * ng]     = r0;  bf1[2 * ng]     = r1;
                bf0[2 * ng + 1] = r2;  bf1[2 * ng + 1] = r3;
            }
            #pragma unroll
            for (int mi = 0; mi < 2; mi++)
                #pragma unroll
                for (int ni = 0; ni < 8; ni++)
                    asm volatile(
                        "mma.sync.aligned.m16n8k16.row.col.f32.bf16.bf16.f32 "
                        "{%0,%1,%2,%3}, {%4,%5,%6,%7}, {%8,%9}, {%0,%1,%2,%3};"
                        : "+f"(acc[mi][ni][0]), "+f"(acc[mi][ni][1]),
                          "+f"(acc[mi][ni][2]), "+f"(acc[mi][ni][3])
                        : "r"(af[mi][0]), "r"(af[mi][1]), "r"(af[mi][2]), "r"(af[mi][3]),
                          "r"(bf0[ni]), "r"(bf1[ni]));
        }
        __syncthreads();
        buf ^= 1;
    }

    // epilogue: add bias, fp32 store
    const int row_base = bm + wm + (lane >> 2);
    const int col_base = bn + wn + (lane & 3) * 2;
    #pragma unroll
    for (int ni = 0; ni < 8; ni++) {
        int col = col_base + ni * 8;
        float b0 = bias[col], b1 = bias[col + 1];
        #pragma unroll
        for (int mi = 0; mi < 2; mi++) {
            int r0 = row_base + mi * 16;
            *(float2*)&C[(size_t)r0 * GEMM_N + col] =
                make_float2(acc[mi][ni][0] + b0, acc[mi][ni][1] + b1);
            *(float2*)&C[(size_t)(r0 + 8) * GEMM_N + col] =
                make_float2(acc[mi][ni][2] + b0, acc[mi][ni][3] + b1);
        }
    }
    #undef LOAD_STAGE
}

// ============================================================
// Flash attention (causal), fp32. One thread per q-row.
// 4 independent dot accumulators (breaks the RAW FFMA chain);
// heavy causal tiles scheduled first (reversed block order).
// ============================================================
#define KV_STRIDE 68
#define SS_STRIDE 65
#define ATTN_SMEM_BYTES ((2 * 64 * KV_STRIDE + 128 * SS_STRIDE) * 4)

__global__ __launch_bounds__(128, 2) void attn_kernel(
    const float* __restrict__ Q, const float* __restrict__ K,
    const float* __restrict__ V, float* __restrict__ O)
{
    extern __shared__ float smem[];
    float* Ks = smem;
    float* Vs = smem + 64 * KV_STRIDE;
    float* Sc = smem + 2 * 64 * KV_STRIDE;

    const int tid = threadIdx.x;
    const int qt  = gridDim.x - 1 - blockIdx.x;   // big tiles first
    const int q0  = qt * 128;
    const int h   = blockIdx.y;
    const int b   = blockIdx.z;

    const float* Qb = Q + ((size_t)b * SS) * EE + h * DD;
    const float* Kb = K + ((size_t)b * SS) * EE + h * DD;
    const float* Vb = V + ((size_t)b * SS) * EE + h * DD;
    float*       Ob = O + ((size_t)b * SS) * EE + h * DD;

    for (int idx = tid; idx < 128 * 64; idx += 128) {
        int r = idx >> 6, d = idx & 63;
        Sc[r * SS_STRIDE + d] = Qb[(size_t)(q0 + r) * EE + d];
    }
    __syncthreads();

    float q[64];
    #pragma unroll
    for (int d = 0; d < 64; d++) q[d] = Sc[tid * SS_STRIDE + d];

    float o[64];
    #pragma unroll
    for (int d = 0; d < 64; d++) o[d] = 0.f;
    float m = -INFINITY, l = 0.f;

    const int grow   = q0 + tid;
    const int ktiles = q0 / 64 + 2;

    for (int kt = 0; kt < ktiles; kt++) {
        __syncthreads();
        for (int idx = tid; idx < 64 * 64; idx += 128) {
            int r = idx >> 6, d = idx & 63;
            size_t g = (size_t)(kt * 64 + r) * EE + d;
            Ks[r * KV_STRIDE + d] = Kb[g];
            Vs[r * KV_STRIDE + d] = Vb[g];
        }
        __syncthreads();

        int jmax = grow - kt * 64;
        if (jmax >= 0) {
            if (jmax > 63) jmax = 63;
            float mnew = m;
            for (int j = 0; j <= jmax; j++) {
                const float4* kr = (const float4*)(Ks + j * KV_STRIDE);
                float sx = 0.f, sy = 0.f, sz = 0.f, sw = 0.f;
                #pragma unroll
                for (int d4 = 0; d4 < 16; d4++) {
                    float4 kv = kr[d4];
                    sx = fmaf(q[4 * d4 + 0], kv.x, sx);
                    sy = fmaf(q[4 * d4 + 1], kv.y, sy);
                    sz = fmaf(q[4 * d4 + 2], kv.z, sz);
                    sw = fmaf(q[4 * d4 + 3], kv.w, sw);
                }
                float s = ((sx + sy) + (sz + sw)) * SCALE;
                Sc[tid * SS_STRIDE + j] = s;
                mnew = fmaxf(mnew, s);
            }
            float corr = __expf(m - mnew);
            l *= corr;
            #pragma unroll
            for (int d = 0; d < 64; d++) o[d] *= corr;
            for (int j = 0; j <= jmax; j++) {
                float p = __expf(Sc[tid * SS_STRIDE + j] - mnew);
                l += p;
                const float4* vr = (const float4*)(Vs + j * KV_STRIDE);
                #pragma unroll
                for (int d4 = 0; d4 < 16; d4++) {
                    float4 vv = vr[d4];
                    o[4 * d4 + 0] += p * vv.x;
                    o[4 * d4 + 1] += p * vv.y;
                    o[4 * d4 + 2] += p * vv.z;
                    o[4 * d4 + 3] += p * vv.w;
                }
            }
            m = mnew;
        }
    }

    __syncthreads();
    float inv = 1.0f / l;
    #pragma unroll
    for (int d = 0; d < 64; d++) Sc[tid * SS_STRIDE + d] = o[d] * inv;
    __syncthreads();
    for (int idx = tid; idx < 128 * 64; idx += 128) {
        int r = idx >> 6, d = idx & 63;
        Ob[(size_t)(q0 + r) * EE + d] = Sc[r * SS_STRIDE + d];
    }
}

// ============================================================
// Host launcher
// ============================================================
extern "C" void kernel_launch(void* const* d_in, const int* in_sizes, int n_in,
                              void* d_out, int out_size)
{
    (void)in_sizes; (void)n_in; (void)out_size;
    const float* x  = (const float*)d_in[0];
    const float* Wq = (const float*)d_in[1];
    const float* bq = (const float*)d_in[2];
    const float* Wk = (const float*)d_in[3];
    const float* bk = (const float*)d_in[4];
    const float* Wv = (const float*)d_in[5];
    const float* bv = (const float*)d_in[6];
    const float* Wo = (const float*)d_in[7];
    const float* bo = (const float*)d_in[8];
    float* out = (float*)d_out;

    float *Qp, *Kp, *Vp, *Ap;
    __nv_bfloat16 *A3p, *B3p;
    cudaGetSymbolAddress((void**)&Qp, g_Q);
    cudaGetSymbolAddress((void**)&Kp, g_K);
    cudaGetSymbolAddress((void**)&Vp, g_V);
    cudaGetSymbolAddress((void**)&Ap, g_A);
    cudaGetSymbolAddress((void**)&A3p, g_A3);
    cudaGetSymbolAddress((void**)&B3p, g_B3);

    cudaFuncSetAttribute(attn_kernel,
                         cudaFuncAttributeMaxDynamicSharedMemorySize,
                         ATTN_SMEM_BYTES);

    const size_t B3SZ = (size_t)GEMM_K * GEMM_N;

    // split x and the four weights into bf16x3 layouts
    split_a3_kernel<<<(MM * EE + 255) / 256, 256>>>(x, A3p);
    split_b3_kernel<<<(EE * EE + 255) / 256, 256>>>(Wq, B3p + 0 * B3SZ);
    split_b3_kernel<<<(EE * EE + 255) / 256, 256>>>(Wk, B3p + 1 * B3SZ);
    split_b3_kernel<<<(EE * EE + 255) / 256, 256>>>(Wv, B3p + 2 * B3SZ);
    split_b3_kernel<<<(EE * EE + 255) / 256, 256>>>(Wo, B3p + 3 * B3SZ);

    dim3 gg(GEMM_N / 128, MM / 128);   // (8, 32)
    gemm_bf16x3_kernel<<<gg, 256>>>(A3p, B3p + 0 * B3SZ, bq, Qp);
    gemm_bf16x3_kernel<<<gg, 256>>>(A3p, B3p + 1 * B3SZ, bk, Kp);
    gemm_bf16x3_kernel<<<gg, 256>>>(A3p, B3p + 2 * B3SZ, bv, Vp);

    dim3 ga(SS / 128, HH, BB);         // (16, 16, 2)
    attn_kernel<<<ga, 128, ATTN_SMEM_BYTES>>>(Qp, Kp, Vp, Ap);

    split_a3_kernel<<<(MM * EE + 255) / 256, 256>>>(Ap, A3p);
    gemm_bf16x3_kernel<<<gg, 256>>>(A3p, B3p + 3 * B3SZ, bo, out);
}

// round 5
// speedup vs baseline: 2.9447x; 2.3108x over previous
#include <cuda_runtime.h>
#include <cuda_bf16.h>
#include <math.h>
#include <stdint.h>

// Problem constants
#define BB 2
#define SS 2048
#define EE 1024
#define HH 16
#define DD 64
#define MM (BB * SS)
#define SCALE 0.03125f        // 1/sqrt(1024)

#define GEMM_K 3072           // 3*EE (bf16x3 emulation folded into K)
#define GEMM_N 1024

// -------- scratch (static device globals) --------
__device__ __nv_bfloat16 g_A3[(size_t)MM * GEMM_K];        // [M, 3K]  (hi|hi|lo)
__device__ __nv_bfloat16 g_B3[4][(size_t)GEMM_K * GEMM_N]; // [3K, N]  (hi;lo;hi)
__device__ __nv_bfloat16 g_Qhi[MM * EE], g_Qlo[MM * EE];
__device__ __nv_bfloat16 g_Khi[MM * EE], g_Klo[MM * EE];
__device__ __nv_bfloat16 g_Vhi[MM * EE], g_Vlo[MM * EE];

__device__ __forceinline__ uint32_t sptr(const void* p) {
    return (uint32_t)__cvta_generic_to_shared(p);
}

#define LDSM_X4(r0, r1, r2, r3, addr)                                                   \
    asm volatile("ldmatrix.sync.aligned.m8n8.x4.shared.b16 {%0,%1,%2,%3}, [%4];"        \
        : "=r"(r0), "=r"(r1), "=r"(r2), "=r"(r3) : "r"(addr))
#define LDSM_X4_T(r0, r1, r2, r3, addr)                                                 \
    asm volatile("ldmatrix.sync.aligned.m8n8.x4.trans.shared.b16 {%0,%1,%2,%3}, [%4];"  \
        : "=r"(r0), "=r"(r1), "=r"(r2), "=r"(r3) : "r"(addr))
#define MMA16816(d, a, b0, b1)                                                          \
    asm volatile("mma.sync.aligned.m16n8k16.row.col.f32.bf16.bf16.f32 "                 \
        "{%0,%1,%2,%3}, {%4,%5,%6,%7}, {%8,%9}, {%0,%1,%2,%3};"                         \
        : "+f"((d)[0]), "+f"((d)[1]), "+f"((d)[2]), "+f"((d)[3])                        \
        : "r"((a)[0]), "r"((a)[1]), "r"((a)[2]), "r"((a)[3]), "r"(b0), "r"(b1))

__device__ __forceinline__ uint32_t packbf(float a, float b) {
    __nv_bfloat162 h = __floats2bfloat162_rn(a, b);
    return *(uint32_t*)&h;
}

// ============================================================
// Split kernels
// ============================================================
__global__ void split_a3_kernel(const float* __restrict__ X,
                                __nv_bfloat16* __restrict__ A3)
{
    int idx = blockIdx.x * 256 + threadIdx.x;
    if (idx >= MM * EE) return;
    int r = idx >> 10, k = idx & 1023;
    float x = X[idx];
    __nv_bfloat16 hi = __float2bfloat16(x);
    __nv_bfloat16 lo = __float2bfloat16(x - __bfloat162float(hi));
    size_t base = (size_t)r * GEMM_K;
    A3[base + k]        = hi;
    A3[base + 1024 + k] = hi;
    A3[base + 2048 + k] = lo;
}

__global__ void split_b3_kernel(const float* __restrict__ W,
                                __nv_bfloat16* __restrict__ B3)
{
    int idx = blockIdx.x * 256 + threadIdx.x;
    if (idx >= EE * EE) return;
    float w = W[idx];
    __nv_bfloat16 hi = __float2bfloat16(w);
    __nv_bfloat16 lo = __float2bfloat16(w - __bfloat162float(hi));
    B3[idx]               = hi;
    B3[idx + 1024 * 1024] = lo;
    B3[idx + 2048 * 1024] = hi;
}

// ============================================================
// bf16x3 GEMM (HMMA m16n8k16), fp32 accumulate.
// Epilogue: either fp32 (+bias), or bf16 hi/lo of (acc+bias)*scale.
// ============================================================
__global__ __launch_bounds__(256, 2) void gemm_bf16x3_kernel(
    const __nv_bfloat16* __restrict__ A,
    const __nv_bfloat16* __restrict__ B,
    const float* __restrict__ bias, float scale,
    float* __restrict__ Cf,
    __nv_bfloat16* __restrict__ Chi,
    __nv_bfloat16* __restrict__ Clo)
{
    constexpr int BM = 128, BK = 32;
    constexpr int AST = 40;
    constexpr int BST = 136;

    __shared__ __align__(16) __nv_bfloat16 As[2][BM * AST];
    __shared__ __align__(16) __nv_bfloat16 Bs[2][BK * BST];

    const int tid  = threadIdx.x;
    const int lane = tid & 31;
    const int warp = tid >> 5;
    const int bm = blockIdx.y * BM;
    const int bn = blockIdx.x * 128;
    const int wm = (warp >> 1) * 32;
    const int wn = (warp & 1) * 64;

    float acc[2][8][4];
    #pragma unroll
    for (int i = 0; i < 2; i++)
        #pragma unroll
        for (int j = 0; j < 8; j++)
            #pragma unroll
            for (int k = 0; k < 4; k++) acc[i][j][k] = 0.f;

    const int ar0 = tid >> 2,         ak0 = (tid & 3) * 8;
    const int ar1 = (tid + 256) >> 2, ak1 = (tid & 3) * 8;
    const int br0 = tid >> 4,         bn0 = (tid & 15) * 8;
    const int br1 = (tid + 256) >> 4, bn1 = (tid & 15) * 8;

    #define LOAD_STAGE(buf, k0)                                                              \
        do {                                                                                 \
            asm volatile("cp.async.cg.shared.global [%0], [%1], 16;" ::                      \
                "r"(sptr(&As[buf][ar0 * AST + ak0])),                                        \
                "l"(A + (size_t)(bm + ar0) * GEMM_K + (k0) + ak0));                          \
            asm volatile("cp.async.cg.shared.global [%0], [%1], 16;" ::                      \
                "r"(sptr(&As[buf][ar1 * AST + ak1])),                                        \
                "l"(A + (size_t)(bm + ar1) * GEMM_K + (k0) + ak1));                          \
            asm volatile("cp.async.cg.shared.global [%0], [%1], 16;" ::                      \
                "r"(sptr(&Bs[buf][br0 * BST + bn0])),                                        \
                "l"(B + (size_t)((k0) + br0) * GEMM_N + bn + bn0));                          \
            asm volatile("cp.async.cg.shared.global [%0], [%1], 16;" ::                      \
                "r"(sptr(&Bs[buf][br1 * BST + bn1])),                                        \
                "l"(B + (size_t)((k0) + br1) * GEMM_N + bn + bn1));                          \
        } while (0)

    LOAD_STAGE(0, 0);
    asm volatile("cp.async.commit_group;");

    constexpr int NSTEPS = GEMM_K / BK;
    int buf = 0;

    for (int it = 0; it < NSTEPS; it++) {
        if (it + 1 < NSTEPS) {
            LOAD_STAGE(buf ^ 1, (it + 1) * BK);
            asm volatile("cp.async.commit_group;");
            asm volatile("cp.async.wait_group 1;");
        } else {
            asm volatile("cp.async.wait_group 0;");
        }
        __syncthreads();

        #pragma unroll
        for (int ks = 0; ks < 2; ks++) {
            const int k0 = ks * 16;
            uint32_t af[2][4];
            #pragma unroll
            for (int mi = 0; mi < 2; mi++) {
                uint32_t addr = sptr(&As[buf][(wm + mi * 16 + (lane & 15)) * AST
                                              + k0 + (lane >> 4) * 8]);
                LDSM_X4(af[mi][0], af[mi][1], af[mi][2], af[mi][3], addr);
            }
            uint32_t bf0[8], bf1[8];
            #pragma unroll
            for (int ng = 0; ng < 4; ng++) {
                uint32_t addr = sptr(&Bs[buf][(k0 + (lane & 15)) * BST
                                              + wn + ng * 16 + (lane >> 4) * 8]);
                uint32_t r0, r1, r2, r3;
                LDSM_X4_T(r0, r1, r2, r3, addr);
                bf0[2 * ng]     = r0;  bf1[2 * ng]     = r1;
                bf0[2 * ng + 1] = r2;  bf1[2 * ng + 1] = r3;
            }
            #pragma unroll
            for (int mi = 0; mi < 2; mi++)
                #pragma unroll
                for (int ni = 0; ni < 8; ni++)
                    MMA16816(acc[mi][ni], af[mi], bf0[ni], bf1[ni]);
        }
        __syncthreads();
        buf ^= 1;
    }

    const int row_base = bm + wm + (lane >> 2);
    const int col_base = bn + wn + (lane & 3) * 2;
    #pragma unroll
    for (int ni = 0; ni < 8; ni++) {
        int col = col_base + ni * 8;
        float b0 = bias[col], b1 = bias[col + 1];
        #pragma unroll
        for (int mi = 0; mi < 2; mi++) {
            #pragma unroll
            for (int half = 0; half < 2; half++) {
                int r = row_base + mi * 16 + half * 8;
                float y0 = acc[mi][ni][2 * half]     + b0;
                float y1 = acc[mi][ni][2 * half + 1] + b1;
                if (Cf) {
                    *(float2*)&Cf[(size_t)r * GEMM_N + col] = make_float2(y0, y1);
                } else {
                    y0 *= scale; y1 *= scale;
                    __nv_bfloat162 hh = __floats2bfloat162_rn(y0, y1);
                    __nv_bfloat162 ll = __floats2bfloat162_rn(
                        y0 - __bfloat162float(hh.x), y1 - __bfloat162float(hh.y));
                    *(__nv_bfloat162*)&Chi[(size_t)r * GEMM_N + col] = hh;
                    *(__nv_bfloat162*)&Clo[(size_t)r * GEMM_N + col] = ll;
                }
            }
        }
    }
    #undef LOAD_STAGE
}

// ============================================================
// Tensor-core flash attention (causal), bf16x3 split precision.
// Block = 4 warps = 64 q rows (16 per warp). kv tiles of 64.
// Writes o-proj A operand (A3 layout: hi|hi|lo) directly.
// ============================================================
#define KVS 72   // smem row stride (bf16): 144B -> conflict-free LDSM

__global__ __launch_bounds__(128) void attn_mma_kernel(
    const __nv_bfloat16* __restrict__ Qhi, const __nv_bfloat16* __restrict__ Qlo,
    const __nv_bfloat16* __restrict__ Khi, const __nv_bfloat16* __restrict__ Klo,
    const __nv_bfloat16* __restrict__ Vhi, const __nv_bfloat16* __restrict__ Vlo,
    __nv_bfloat16* __restrict__ A3)
{
    __shared__ __align__(16) __nv_bfloat16 sKh[64 * KVS], sKl[64 * KVS];
    __shared__ __align__(16) __nv_bfloat16 sVh[64 * KVS], sVl[64 * KVS];

    const int tid  = threadIdx.x;
    const int lane = tid & 31;
    const int warp = tid >> 5;
    const int qt = gridDim.x - 1 - blockIdx.x;   // heavy tiles first
    const int h  = blockIdx.y;
    const int b  = blockIdx.z;
    const size_t tok0 = (size_t)b * SS + qt * 64;
    const int hcol = h * 64;

    // ---- stage Q tile (hi/lo) through sKh/sKl, ldmatrix to registers
    #pragma unroll
    for (int i = 0; i < 4; i++) {
        int idx = tid + i * 128;                 // 64 rows x 8 chunks
        int r = idx >> 3, c = (idx & 7) * 8;
        *(uint4*)(sKh + r * KVS + c) = *(const uint4*)(Qhi + (tok0 + r) * EE + hcol + c);
        *(uint4*)(sKl + r * KVS + c) = *(const uint4*)(Qlo + (tok0 + r) * EE + hcol + c);
    }
    __syncthreads();

    uint32_t qh[4][4], ql[4][4];
    {
        int r = warp * 16 + (lane & 15);
        #pragma unroll
        for (int kt = 0; kt < 4; kt++) {
            int c = kt * 16 + (lane >> 4) * 8;
            LDSM_X4(qh[kt][0], qh[kt][1], qh[kt][2], qh[kt][3], sptr(sKh + r * KVS + c));
            LDSM_X4(ql[kt][0], ql[kt][1], ql[kt][2], ql[kt][3], sptr(sKl + r * KVS + c));
        }
    }

    float o[8][4];
    #pragma unroll
    for (int ni = 0; ni < 8; ni++)
        #pragma unroll
        for (int j = 0; j < 4; j++) o[ni][j] = 0.f;
    float m0 = -1e30f, m1 = -1e30f, l0 = 0.f, l1 = 0.f;
    const int r0loc = warp * 16 + (lane >> 2);   // local q row of c0/c1

    for (int t = 0; t <= qt; t++) {
        __syncthreads();
        #pragma unroll
        for (int i = 0; i < 4; i++) {
            int idx = tid + i * 128;
            int r = idx >> 3, c = (idx & 7) * 8;
            size_t g = ((size_t)b * SS + t * 64 + r) * EE + hcol + c;
            *(uint4*)(sKh + r * KVS + c) = *(const uint4*)(Khi + g);
            *(uint4*)(sKl + r * KVS + c) = *(const uint4*)(Klo + g);
            *(uint4*)(sVh + r * KVS + c) = *(const uint4*)(Vhi + g);
            *(uint4*)(sVl + r * KVS + c) = *(const uint4*)(Vlo + g);
        }
        __syncthreads();

        // ---- scores: S = Qhi*Khi + Qlo*Khi + Qhi*Klo
        float s[8][4];
        #pragma unroll
        for (int ni = 0; ni < 8; ni++)
            #pragma unroll
            for (int j = 0; j < 4; j++) s[ni][j] = 0.f;

        #pragma unroll
        for (int kt = 0; kt < 4; kt++) {
            uint32_t bh[8][2], bl[8][2];
            #pragma unroll
            for (int g = 0; g < 4; g++) {
                int row = g * 16 + (lane & 7) + ((lane & 16) >> 1);
                int cx  = (kt * 2 + ((lane >> 3) & 1)) * 8;
                uint32_t r0, r1, r2, r3;
                LDSM_X4(r0, r1, r2, r3, sptr(sKh + row * KVS + cx));
                bh[2 * g][0] = r0; bh[2 * g][1] = r1;
                bh[2 * g + 1][0] = r2; bh[2 * g + 1][1] = r3;
                LDSM_X4(r0, r1, r2, r3, sptr(sKl + row * KVS + cx));
                bl[2 * g][0] = r0; bl[2 * g][1] = r1;
                bl[2 * g + 1][0] = r2; bl[2 * g + 1][1] = r3;
            }
            #pragma unroll
            for (int ni = 0; ni < 8; ni++) {
                MMA16816(s[ni], qh[kt], bh[ni][0], bh[ni][1]);
                MMA16816(s[ni], ql[kt], bh[ni][0], bh[ni][1]);
                MMA16816(s[ni], qh[kt], bl[ni][0], bl[ni][1]);
            }
        }

        // ---- causal mask on the diagonal tile
        if (t == qt) {
            #pragma unroll
            for (int ni = 0; ni < 8; ni++) {
                int c0 = ni * 8 + 2 * (lane & 3);
                if (c0     > r0loc)     s[ni][0] = -1e30f;
                if (c0 + 1 > r0loc)     s[ni][1] = -1e30f;
                if (c0     > r0loc + 8) s[ni][2] = -1e30f;
                if (c0 + 1 > r0loc + 8) s[ni][3] = -1e30f;
            }
        }

        // ---- online softmax
        float tm0 = -1e30f, tm1 = -1e30f;
        #pragma unroll
        for (int ni = 0; ni < 8; ni++) {
            tm0 = fmaxf(tm0, fmaxf(s[ni][0], s[ni][1]));
            tm1 = fmaxf(tm1, fmaxf(s[ni][2], s[ni][3]));
        }
        tm0 = fmaxf(tm0, __shfl_xor_sync(0xffffffffu, tm0, 1));
        tm0 = fmaxf(tm0, __shfl_xor_sync(0xffffffffu, tm0, 2));
        tm1 = fmaxf(tm1, __shfl_xor_sync(0xffffffffu, tm1, 1));
        tm1 = fmaxf(tm1, __shfl_xor_sync(0xffffffffu, tm1, 2));
        float mn0 = fmaxf(m0, tm0), mn1 = fmaxf(m1, tm1);
        float cf0 = __expf(m0 - mn0), cf1 = __expf(m1 - mn1);
        l0 *= cf0; l1 *= cf1;
        #pragma unroll
        for (int ni = 0; ni < 8; ni++) {
            o[ni][0] *= cf0; o[ni][1] *= cf0;
            o[ni][2] *= cf1; o[ni][3] *= cf1;
        }
        #pragma unroll
        for (int ni = 0; ni < 8; ni++) {
            s[ni][0] = __expf(s[ni][0] - mn0);
            s[ni][1] = __expf(s[ni][1] - mn0);
            s[ni][2] = __expf(s[ni][2] - mn1);
            s[ni][3] = __expf(s[ni][3] - mn1);
            l0 += s[ni][0] + s[ni][1];
            l1 += s[ni][2] + s[ni][3];
        }
        m0 = mn0; m1 = mn1;

        // ---- O += P*V  (Phi*Vhi + Plo*Vhi + Phi*Vlo)
        #pragma unroll
        for (int kt = 0; kt < 4; kt++) {
            uint32_t ah[4], al[4];
            {
                float f0 = s[2 * kt][0], f1 = s[2 * kt][1];
                float f2 = s[2 * kt][2], f3 = s[2 * kt][3];
                float g0 = s[2 * kt + 1][0], g1 = s[2 * kt + 1][1];
                float g2 = s[2 * kt + 1][2], g3 = s[2 * kt + 1][3];
                ah[0] = packbf(f0, f1); ah[1] = packbf(f2, f3);
                ah[2] = packbf(g0, g1); ah[3] = packbf(g2, g3);
                __nv_bfloat162 h;
                h = *(__nv_bfloat162*)&ah[0];
                al[0] = packbf(f0 - __bfloat162float(h.x), f1 - __bfloat162float(h.y));
                h = *(__nv_bfloat162*)&ah[1];
                al[1] = packbf(f2 - __bfloat162float(h.x), f3 - __bfloat162float(h.y));
                h = *(__nv_bfloat162*)&ah[2];
                al[2] = packbf(g0 - __bfloat162float(h.x), g1 - __bfloat162float(h.y));
                h = *(__nv_bfloat162*)&ah[3];
                al[3] = packbf(g2 - __bfloat162float(h.x), g3 - __bfloat162float(h.y));
            }
            uint32_t vh[8][2], vl[8][2];
            #pragma unroll
            for (int g = 0; g < 4; g++) {
                int row = kt * 16 + (lane & 15);
                int cx  = (g * 2 + (lane >> 4)) * 8;
                uint32_t r0, r1, r2, r3;
                LDSM_X4_T(r0, r1, r2, r3, sptr(sVh + row * KVS + cx));
                vh[2 * g][0] = r0; vh[2 * g][1] = r1;
                vh[2 * g + 1][0] = r2; vh[2 * g + 1][1] = r3;
                LDSM_X4_T(r0, r1, r2, r3, sptr(sVl + row * KVS + cx));
                vl[2 * g][0] = r0; vl[2 * g][1] = r1;
                vl[2 * g + 1][0] = r2; vl[2 * g + 1][1] = r3;
            }
            #pragma unroll
            for (int ni = 0; ni < 8; ni++) {
                MMA16816(o[ni], ah, vh[ni][0], vh[ni][1]);
                MMA16816(o[ni], al, vh[ni][0], vh[ni][1]);
                MMA16816(o[ni], ah, vl[ni][0], vl[ni][1]);
            }
        }
    }

    // ---- finalize: normalize, write A3 (hi|hi|lo) for the O projection
    l0 += __shfl_xor_sync(0xffffffffu, l0, 1);
    l0 += __shfl_xor_sync(0xffffffffu, l0, 2);
    l1 += __shfl_xor_sync(0xffffffffu, l1, 1);
    l1 += __shfl_xor_sync(0xffffffffu, l1, 2);
    float i0 = 1.f / l0, i1 = 1.f / l1;

    size_t row0 = tok0 + warp * 16 + (lane >> 2);
    size_t row1 = row0 + 8;
    #pragma unroll
    for (int ni = 0; ni < 8; ni++) {
        int col = hcol + ni * 8 + 2 * (lane & 3);
        #pragma unroll
        for (int half = 0; half < 2; half++) {
            size_t r = half ? row1 : row0;
            float inv = half ? i1 : i0;
            float y0 = o[ni][2 * half] * inv, y1 = o[ni][2 * half + 1] * inv;
            __nv_bfloat162 hh = __floats2bfloat162_rn(y0, y1);
            __nv_bfloat162 ll = __floats2bfloat162_rn(
                y0 - __bfloat162float(hh.x), y1 - __bfloat162float(hh.y));
            __nv_bfloat16* base = A3 + r * GEMM_K + col;
            *(__nv_bfloat162*)(base)        = hh;
            *(__nv_bfloat162*)(base + 1024) = hh;
            *(__nv_bfloat162*)(base + 2048) = ll;
        }
    }
}

// ============================================================
// Host launcher
// ============================================================
extern "C" void kernel_launch(void* const* d_in, const int* in_sizes, int n_in,
                              void* d_out, int out_size)
{
    (void)in_sizes; (void)n_in; (void)out_size;
    const float* x  = (const float*)d_in[0];
    const float* Wq = (const float*)d_in[1];
    const float* bq = (const float*)d_in[2];
    const float* Wk = (const float*)d_in[3];
    const float* bk = (const float*)d_in[4];
    const float* Wv = (const float*)d_in[5];
    const float* bv = (const float*)d_in[6];
    const float* Wo = (const float*)d_in[7];
    const float* bo = (const float*)d_in[8];
    float* out = (float*)d_out;

    __nv_bfloat16 *A3p, *B3p, *Qh, *Ql, *Kh, *Kl, *Vh, *Vl;
    cudaGetSymbolAddress((void**)&A3p, g_A3);
    cudaGetSymbolAddress((void**)&B3p, g_B3);
    cudaGetSymbolAddress((void**)&Qh, g_Qhi);
    cudaGetSymbolAddress((void**)&Ql, g_Qlo);
    cudaGetSymbolAddress((void**)&Kh, g_Khi);
    cudaGetSymbolAddress((void**)&Kl, g_Klo);
    cudaGetSymbolAddress((void**)&Vh, g_Vhi);
    cudaGetSymbolAddress((void**)&Vl, g_Vlo);

    const size_t B3SZ = (size_t)GEMM_K * GEMM_N;

    split_a3_kernel<<<(MM * EE + 255) / 256, 256>>>(x, A3p);
    split_b3_kernel<<<(EE * EE + 255) / 256, 256>>>(Wq, B3p + 0 * B3SZ);
    split_b3_kernel<<<(EE * EE + 255) / 256, 256>>>(Wk, B3p + 1 * B3SZ);
    split_b3_kernel<<<(EE * EE + 255) / 256, 256>>>(Wv, B3p + 2 * B3SZ);
    split_b3_kernel<<<(EE * EE + 255) / 256, 256>>>(Wo, B3p + 3 * B3SZ);

    dim3 gg(GEMM_N / 128, MM / 128);   // (8, 32)
    gemm_bf16x3_kernel<<<gg, 256>>>(A3p, B3p + 0 * B3SZ, bq, SCALE, nullptr, Qh, Ql);
    gemm_bf16x3_kernel<<<gg, 256>>>(A3p, B3p + 1 * B3SZ, bk, 1.0f,  nullptr, Kh, Kl);
    gemm_bf16x3_kernel<<<gg, 256>>>(A3p, B3p + 2 * B3SZ, bv, 1.0f,  nullptr, Vh, Vl);

    dim3 ga(SS / 64, HH, BB);          // (32, 16, 2)
    attn_mma_kernel<<<ga, 128>>>(Qh, Ql, Kh, Kl, Vh, Vl, A3p);

    gemm_bf16x3_kernel<<<gg, 256>>>(A3p, B3p + 3 * B3SZ, bo, 1.0f, out, nullptr, nullptr);
}

// round 7
// speedup vs baseline: 3.0705x; 1.0428x over previous
#include <cuda_runtime.h>
#include <cuda_bf16.h>
#include <math.h>
#include <stdint.h>

// Problem constants
#define BB 2
#define SS 2048
#define EE 1024
#define HH 16
#define DD 64
#define MM (BB * SS)
#define SCALE 0.03125f        // 1/sqrt(1024)

#define GEMM_K 3072           // 3*EE (bf16x3 emulation folded into K)

// -------- scratch (static device globals) --------
__device__ __nv_bfloat16 g_A3[(size_t)MM * GEMM_K];          // [M, 3K] (hi|hi|lo)
__device__ __nv_bfloat16 g_B3f[(size_t)GEMM_K * 3072];       // QKV fused: [3K, 3072] (hi;lo;hi)
__device__ __nv_bfloat16 g_B3o[(size_t)GEMM_K * 1024];       // O proj:   [3K, 1024]
__device__ __nv_bfloat16 g_Qhi[MM * EE], g_Qlo[MM * EE];
__device__ __nv_bfloat16 g_Khi[MM * EE], g_Klo[MM * EE];
__device__ __nv_bfloat16 g_Vhi[MM * EE], g_Vlo[MM * EE];

__device__ __forceinline__ uint32_t sptr(const void* p) {
    return (uint32_t)__cvta_generic_to_shared(p);
}

#define LDSM_X4(r0, r1, r2, r3, addr)                                                   \
    asm volatile("ldmatrix.sync.aligned.m8n8.x4.shared.b16 {%0,%1,%2,%3}, [%4];"        \
        : "=r"(r0), "=r"(r1), "=r"(r2), "=r"(r3) : "r"(addr))
#define LDSM_X4_T(r0, r1, r2, r3, addr)                                                 \
    asm volatile("ldmatrix.sync.aligned.m8n8.x4.trans.shared.b16 {%0,%1,%2,%3}, [%4];"  \
        : "=r"(r0), "=r"(r1), "=r"(r2), "=r"(r3) : "r"(addr))
#define MMA16816(d, a, b0, b1)                                                          \
    asm volatile("mma.sync.aligned.m16n8k16.row.col.f32.bf16.bf16.f32 "                 \
        "{%0,%1,%2,%3}, {%4,%5,%6,%7}, {%8,%9}, {%0,%1,%2,%3};"                         \
        : "+f"((d)[0]), "+f"((d)[1]), "+f"((d)[2]), "+f"((d)[3])                        \
        : "r"((a)[0]), "r"((a)[1]), "r"((a)[2]), "r"((a)[3]), "r"(b0), "r"(b1))

__device__ __forceinline__ uint32_t packbf(float a, float b) {
    __nv_bfloat162 h = __floats2bfloat162_rn(a, b);
    return *(uint32_t*)&h;
}

// ============================================================
// Split kernels (vectorized)
// ============================================================
__global__ void split_a3_kernel(const float* __restrict__ X,
                                __nv_bfloat16* __restrict__ A3)
{
    int idx = blockIdx.x * 256 + threadIdx.x;     // over MM*EE/4
    if (idx >= MM * EE / 4) return;
    int i4 = idx * 4;
    int r = i4 >> 10, k = i4 & 1023;
    float4 x = *(const float4*)(X + i4);
    __nv_bfloat162 h0 = __floats2bfloat162_rn(x.x, x.y);
    __nv_bfloat162 h1 = __floats2bfloat162_rn(x.z, x.w);
    __nv_bfloat162 l0 = __floats2bfloat162_rn(x.x - __bfloat162float(h0.x),
                                              x.y - __bfloat162float(h0.y));
    __nv_bfloat162 l1 = __floats2bfloat162_rn(x.z - __bfloat162float(h1.x),
                                              x.w - __bfloat162float(h1.y));
    __nv_bfloat16* p = g_A3 + (size_t)r * GEMM_K + k;
    *(__nv_bfloat162*)(p)          = h0;
    *(__nv_bfloat162*)(p + 2)      = h1;
    *(__nv_bfloat162*)(p + 1024)   = h0;
    *(__nv_bfloat162*)(p + 1026)   = h1;
    *(__nv_bfloat162*)(p + 2048)   = l0;
    *(__nv_bfloat162*)(p + 2050)   = l1;
    (void)A3;
}

// W[1024,1024] fp32 -> B3[3K, ldn] at column offset coff (hi ; lo ; hi)
__global__ void split_b3_kernel(const float* __restrict__ W,
                                __nv_bfloat16* __restrict__ B3,
                                int ldn, int coff)
{
    int idx = blockIdx.x * 256 + threadIdx.x;     // over 1024*1024/4
    if (idx >= EE * EE / 4) return;
    int i4 = idx * 4;
    int k = i4 >> 10, n = i4 & 1023;
    float4 w = *(const float4*)(W + i4);
    __nv_bfloat162 h0 = __floats2bfloat162_rn(w.x, w.y);
    __nv_bfloat162 h1 = __floats2bfloat162_rn(w.z, w.w);
    __nv_bfloat162 l0 = __floats2bfloat162_rn(w.x - __bfloat162float(h0.x),
                                              w.y - __bfloat162float(h0.y));
    __nv_bfloat162 l1 = __floats2bfloat162_rn(w.z - __bfloat162float(h1.x),
                                              w.w - __bfloat162float(h1.y));
    __nv_bfloat16* p = B3 + (size_t)k * ldn + coff + n;
    size_t s = (size_t)1024 * ldn;
    *(__nv_bfloat162*)(p)              = h0;
    *(__nv_bfloat162*)(p + 2)          = h1;
    *(__nv_bfloat162*)(p + s)          = l0;
    *(__nv_bfloat162*)(p + s + 2)      = l1;
    *(__nv_bfloat162*)(p + 2 * s)      = h0;
    *(__nv_bfloat162*)(p + 2 * s + 2)  = h1;
}

// ============================================================
// bf16x3 GEMM (HMMA m16n8k16), fp32 accumulate.
// CTA tile 128x128, 128 threads (4 warps, 2m x 2n, 64x64/warp),
// BK=32, 3-stage cp.async. Segment-aware epilogue (QKV fused).
// ============================================================
#define AST 40     // A smem row stride (bf16)
#define BST 136    // B smem row stride (bf16)
#define A_SBYTES (128 * AST * 2)                 // 10240
#define B_SBYTES (32 * BST * 2)                  // 8704
#define STAGE_BYTES (A_SBYTES + B_SBYTES)        // 18944
#define G_SMEM_BYTES (3 * STAGE_BYTES)           // 56832

__global__ __launch_bounds__(128, 2) void gemm_hmma_kernel(
    const __nv_bfloat16* __restrict__ A,
    const __nv_bfloat16* __restrict__ B, int ldb,
    const float* __restrict__ bias0, const float* __restrict__ bias1,
    const float* __restrict__ bias2, float scale0,
    float* __restrict__ Cf,
    __nv_bfloat16* __restrict__ H0, __nv_bfloat16* __restrict__ L0,
    __nv_bfloat16* __restrict__ H1, __nv_bfloat16* __restrict__ L1,
    __nv_bfloat16* __restrict__ H2, __nv_bfloat16* __restrict__ L2)
{
    extern __shared__ __align__(16) char dsm[];

    const int tid  = threadIdx.x;
    const int lane = tid & 31;
    const int warp = tid >> 5;
    const int bm = blockIdx.y * 128;
    const int bn = blockIdx.x * 128;
    const int wm = (warp >> 1) * 64;
    const int wn = (warp & 1) * 64;

    float acc[4][8][4];
    #pragma unroll
    for (int i = 0; i < 4; i++)
        #pragma unroll
        for (int j = 0; j < 8; j++)
            #pragma unroll
            for (int k = 0; k < 4; k++) acc[i][j][k] = 0.f;

    auto As = [&](int s) { return (__nv_bfloat16*)(dsm + s * STAGE_BYTES); };
    auto Bs = [&](int s) { return (__nv_bfloat16*)(dsm + s * STAGE_BYTES + A_SBYTES); };

    auto gload = [&](int s, int it) {
        const int k0 = it * 32;
        __nv_bfloat16* as = As(s);
        __nv_bfloat16* bs = Bs(s);
        #pragma unroll
        for (int i = 0; i < 4; i++) {
            int c = tid + i * 128;                // 512 A chunks
            int r = c >> 2, kk = (c & 3) * 8;
            asm volatile("cp.async.cg.shared.global [%0], [%1], 16;" ::
                "r"(sptr(as + r * AST + kk)),
                "l"(A + (size_t)(bm + r) * GEMM_K + k0 + kk));
        }
        #pragma unroll
        for (int i = 0; i < 4; i++) {
            int c = tid + i * 128;                // 512 B chunks
            int r = c >> 4, nn = (c & 15) * 8;
            asm volatile("cp.async.cg.shared.global [%0], [%1], 16;" ::
                "r"(sptr(bs + r * BST + nn)),
                "l"(B + (size_t)(k0 + r) * ldb + bn + nn));
        }
        asm volatile("cp.async.commit_group;" ::: "memory");
    };

    constexpr int NSTEPS = GEMM_K / 32;  // 96
    gload(0, 0);
    gload(1, 1);

    for (int it = 0; it < NSTEPS; it++) {
        const int buf = it % 3;
        if (it + 2 < NSTEPS) {
            gload((it + 2) % 3, it + 2);
            asm volatile("cp.async.wait_group 2;" ::: "memory");
        } else if (it + 1 < NSTEPS) {
            asm volatile("cp.async.wait_group 1;" ::: "memory");
        } else {
            asm volatile("cp.async.wait_group 0;" ::: "memory");
        }
        __syncthreads();

        __nv_bfloat16* as = As(buf);
        __nv_bfloat16* bs = Bs(buf);
        #pragma unroll
        for (int ks = 0; ks < 2; ks++) {
            const int k0 = ks * 16;
            uint32_t af[4][4];
            #pragma unroll
            for (int mi = 0; mi < 4; mi++) {
                uint32_t addr = sptr(as + (wm + mi * 16 + (lane & 15)) * AST
                                        + k0 + (lane >> 4) * 8);
                LDSM_X4(af[mi][0], af[mi][1], af[mi][2], af[mi][3], addr);
            }
            uint32_t bf0[8], bf1[8];
            #pragma unroll
            for (int g = 0; g < 4; g++) {
                uint32_t addr = sptr(bs + (k0 + (lane & 15)) * BST
                                        + wn + g * 16 + (lane >> 4) * 8);
                uint32_t r0, r1, r2, r3;
                LDSM_X4_T(r0, r1, r2, r3, addr);
                bf0[2 * g]     = r0;  bf1[2 * g]     = r1;
                bf0[2 * g + 1] = r2;  bf1[2 * g + 1] = r3;
            }
            #pragma unroll
            for (int mi = 0; mi < 4; mi++)
                #pragma unroll
                for (int ni = 0; ni < 8; ni++)
                    MMA16816(acc[mi][ni], af[mi], bf0[ni], bf1[ni]);
        }
        __syncthreads();
    }

    // ---- segment-aware epilogue
    const int seg = bn >> 10;                    // 0..2 (0 always for O proj)
    const float* bias = (seg == 0) ? bias0 : (seg == 1) ? bias1 : bias2;
    const float scale = (seg == 0) ? scale0 : 1.0f;
    __nv_bfloat16* Hc = (seg == 0) ? H0 : (seg == 1) ? H1 : H2;
    __nv_bfloat16* Lc = (seg == 0) ? L0 : (seg == 1) ? L1 : L2;
    const int lbn = bn & 1023;

    const int row_base = bm + wm + (lane >> 2);
    const int col_base = wn + (lane & 3) * 2;
    #pragma unroll
    for (int ni = 0; ni < 8; ni++) {
        int col = lbn + col_base + ni * 8;
        float b0 = bias[col], b1 = bias[col + 1];
        #pragma unroll
        for (int mi = 0; mi < 4; mi++) {
            #pragma unroll
            for (int half = 0; half < 2; half++) {
                int r = row_base + mi * 16 + half * 8;
                float y0 = acc[mi][ni][2 * half]     + b0;
                float y1 = acc[mi][ni][2 * half + 1] + b1;
                if (Cf) {
                    *(float2*)&Cf[(size_t)r * EE + col] = make_float2(y0, y1);
                } else {
                    y0 *= scale; y1 *= scale;
                    __nv_bfloat162 hh = __floats2bfloat162_rn(y0, y1);
                    __nv_bfloat162 ll = __floats2bfloat162_rn(
                        y0 - __bfloat162float(hh.x), y1 - __bfloat162float(hh.y));
                    *(__nv_bfloat162*)&Hc[(size_t)r * EE + col] = hh;
                    *(__nv_bfloat162*)&Lc[(size_t)r * EE + col] = ll;
                }
            }
        }
    }
}

// ============================================================
// Tensor-core flash attention (causal), bf16x3 split precision.
// (unchanged from round 5 — proven)
// ============================================================
#define KVS 72

__global__ __launch_bounds__(128) void attn_mma_kernel(
    const __nv_bfloat16* __restrict__ Qhi, const __nv_bfloat16* __restrict__ Qlo,
    const __nv_bfloat16* __restrict__ Khi, const __nv_bfloat16* __restrict__ Klo,
    const __nv_bfloat16* __restrict__ Vhi, const __nv_bfloat16* __restrict__ Vlo,
    __nv_bfloat16* __restrict__ A3)
{
    __shared__ __align__(16) __nv_bfloat16 sKh[64 * KVS], sKl[64 * KVS];
    __shared__ __align__(16) __nv_bfloat16 sVh[64 * KVS], sVl[64 * KVS];

    const int tid  = threadIdx.x;
    const int lane = tid & 31;
    const int warp = tid >> 5;
    const int qt = gridDim.x - 1 - blockIdx.x;
    const int h  = blockIdx.y;
    const int b  = blockIdx.z;
    const size_t tok0 = (size_t)b * SS + qt * 64;
    const int hcol = h * 64;

    #pragma unroll
    for (int i = 0; i < 4; i++) {
        int idx = tid + i * 128;
        int r = idx >> 3, c = (idx & 7) * 8;
        *(uint4*)(sKh + r * KVS + c) = *(const uint4*)(Qhi + (tok0 + r) * EE + hcol + c);
        *(uint4*)(sKl + r * KVS + c) = *(const uint4*)(Qlo + (tok0 + r) * EE + hcol + c);
    }
    __syncthreads();

    uint32_t qh[4][4], ql[4][4];
    {
        int r = warp * 16 + (lane & 15);
        #pragma unroll
        for (int kt = 0; kt < 4; kt++) {
            int c = kt * 16 + (lane >> 4) * 8;
            LDSM_X4(qh[kt][0], qh[kt][1], qh[kt][2], qh[kt][3], sptr(sKh + r * KVS + c));
            LDSM_X4(ql[kt][0], ql[kt][1], ql[kt][2], ql[kt][3], sptr(sKl + r * KVS + c));
        }
    }

    float o[8][4];
    #pragma unroll
    for (int ni = 0; ni < 8; ni++)
        #pragma unroll
        for (int j = 0; j < 4; j++) o[ni][j] = 0.f;
    float m0 = -1e30f, m1 = -1e30f, l0 = 0.f, l1 = 0.f;
    const int r0loc = warp * 16 + (lane >> 2);

    for (int t = 0; t <= qt; t++) {
        __syncthreads();
        #pragma unroll
        for (int i = 0; i < 4; i++) {
            int idx = tid + i * 128;
            int r = idx >> 3, c = (idx & 7) * 8;
            size_t g = ((size_t)b * SS + t * 64 + r) * EE + hcol + c;
            *(uint4*)(sKh + r * KVS + c) = *(const uint4*)(Khi + g);
            *(uint4*)(sKl + r * KVS + c) = *(const uint4*)(Klo + g);
            *(uint4*)(sVh + r * KVS + c) = *(const uint4*)(Vhi + g);
            *(uint4*)(sVl + r * KVS + c) = *(const uint4*)(Vlo + g);
        }
        __syncthreads();

        float s[8][4];
        #pragma unroll
        for (int ni = 0; ni < 8; ni++)
            #pragma unroll
            for (int j = 0; j < 4; j++) s[ni][j] = 0.f;

        #pragma unroll
        for (int kt = 0; kt < 4; kt++) {
            uint32_t bh[8][2], bl[8][2];
            #pragma unroll
            for (int g = 0; g < 4; g++) {
                int row = g * 16 + (lane & 7) + ((lane & 16) >> 1);
                int cx  = (kt * 2 + ((lane >> 3) & 1)) * 8;
                uint32_t r0, r1, r2, r3;
                LDSM_X4(r0, r1, r2, r3, sptr(sKh + row * KVS + cx));
                bh[2 * g][0] = r0; bh[2 * g][1] = r1;
                bh[2 * g + 1][0] = r2; bh[2 * g + 1][1] = r3;
                LDSM_X4(r0, r1, r2, r3, sptr(sKl + row * KVS + cx));
                bl[2 * g][0] = r0; bl[2 * g][1] = r1;
                bl[2 * g + 1][0] = r2; bl[2 * g + 1][1] = r3;
            }
            #pragma unroll
            for (int ni = 0; ni < 8; ni++) {
                MMA16816(s[ni], qh[kt], bh[ni][0], bh[ni][1]);
                MMA16816(s[ni], ql[kt], bh[ni][0], bh[ni][1]);
                MMA16816(s[ni], qh[kt], bl[ni][0], bl[ni][1]);
            }
        }

        if (t == qt) {
            #pragma unroll
            for (int ni = 0; ni < 8; ni++) {
                int c0 = ni * 8 + 2 * (lane & 3);
                if (c0     > r0loc)     s[ni][0] = -1e30f;
                if (c0 + 1 > r0loc)     s[ni][1] = -1e30f;
                if (c0     > r0loc + 8) s[ni][2] = -1e30f;
                if (c0 + 1 > r0loc + 8) s[ni][3] = -1e30f;
            }
        }

        float tm0 = -1e30f, tm1 = -1e30f;
        #pragma unroll
        for (int ni = 0; ni < 8; ni++) {
            tm0 = fmaxf(tm0, fmaxf(s[ni][0], s[ni][1]));
            tm1 = fmaxf(tm1, fmaxf(s[ni][2], s[ni][3]));
        }
        tm0 = fmaxf(tm0, __shfl_xor_sync(0xffffffffu, tm0, 1));
        tm0 = fmaxf(tm0, __shfl_xor_sync(0xffffffffu, tm0, 2));
        tm1 = fmaxf(tm1, __shfl_xor_sync(0xffffffffu, tm1, 1));
        tm1 = fmaxf(tm1, __shfl_xor_sync(0xffffffffu, tm1, 2));
        float mn0 = fmaxf(m0, tm0), mn1 = fmaxf(m1, tm1);
        float cf0 = __expf(m0 - mn0), cf1 = __expf(m1 - mn1);
        l0 *= cf0; l1 *= cf1;
        #pragma unroll
        for (int ni = 0; ni < 8; ni++) {
            o[ni][0] *= cf0; o[ni][1] *= cf0;
            o[ni][2] *= cf1; o[ni][3] *= cf1;
        }
        #pragma unroll
        for (int ni = 0; ni < 8; ni++) {
            s[ni][0] = __expf(s[ni][0] - mn0);
            s[ni][1] = __expf(s[ni][1] - mn0);
            s[ni][2] = __expf(s[ni][2] - mn1);
            s[ni][3] = __expf(s[ni][3] - mn1);
            l0 += s[ni][0] + s[ni][1];
            l1 += s[ni][2] + s[ni][3];
        }
        m0 = mn0; m1 = mn1;

        #pragma unroll
        for (int kt = 0; kt < 4; kt++) {
            uint32_t ah[4], al[4];
            {
                float f0 = s[2 * kt][0], f1 = s[2 * kt][1];
                float f2 = s[2 * kt][2], f3 = s[2 * kt][3];
                float g0 = s[2 * kt + 1][0], g1 = s[2 * kt + 1][1];
                float g2 = s[2 * kt + 1][2], g3 = s[2 * kt + 1][3];
                ah[0] = packbf(f0, f1); ah[1] = packbf(f2, f3);
                ah[2] = packbf(g0, g1); ah[3] = packbf(g2, g3);
                __nv_bfloat162 h2;
                h2 = *(__nv_bfloat162*)&ah[0];
                al[0] = packbf(f0 - __bfloat162float(h2.x), f1 - __bfloat162float(h2.y));
                h2 = *(__nv_bfloat162*)&ah[1];
                al[1] = packbf(f2 - __bfloat162float(h2.x), f3 - __bfloat162float(h2.y));
                h2 = *(__nv_bfloat162*)&ah[2];
                al[2] = packbf(g0 - __bfloat162float(h2.x), g1 - __bfloat162float(h2.y));
                h2 = *(__nv_bfloat162*)&ah[3];
                al[3] = packbf(g2 - __bfloat162float(h2.x), g3 - __bfloat162float(h2.y));
            }
            uint32_t vh[8][2], vl[8][2];
            #pragma unroll
            for (int g = 0; g < 4; g++) {
                int row = kt * 16 + (lane & 15);
                int cx  = (g * 2 + (lane >> 4)) * 8;
                uint32_t r0, r1, r2, r3;
                LDSM_X4_T(r0, r1, r2, r3, sptr(sVh + row * KVS + cx));
                vh[2 * g][0] = r0; vh[2 * g][1] = r1;
                vh[2 * g + 1][0] = r2; vh[2 * g + 1][1] = r3;
                LDSM_X4_T(r0, r1, r2, r3, sptr(sVl + row * KVS + cx));
                vl[2 * g][0] = r0; vl[2 * g][1] = r1;
                vl[2 * g + 1][0] = r2; vl[2 * g + 1][1] = r3;
            }
            #pragma unroll
            for (int ni = 0; ni < 8; ni++) {
                MMA16816(o[ni], ah, vh[ni][0], vh[ni][1]);
                MMA16816(o[ni], al, vh[ni][0], vh[ni][1]);
                MMA16816(o[ni], ah, vl[ni][0], vl[ni][1]);
            }
        }
    }

    l0 += __shfl_xor_sync(0xffffffffu, l0, 1);
    l0 += __shfl_xor_sync(0xffffffffu, l0, 2);
    l1 += __shfl_xor_sync(0xffffffffu, l1, 1);
    l1 += __shfl_xor_sync(0xffffffffu, l1, 2);
    float i0 = 1.f / l0, i1 = 1.f / l1;

    size_t row0 = tok0 + warp * 16 + (lane >> 2);
    size_t row1 = row0 + 8;
    #pragma unroll
    for (int ni = 0; ni < 8; ni++) {
        int col = hcol + ni * 8 + 2 * (lane & 3);
        #pragma unroll
        for (int half = 0; half < 2; half++) {
            size_t r = half ? row1 : row0;
            float inv = half ? i1 : i0;
            float y0 = o[ni][2 * half] * inv, y1 = o[ni][2 * half + 1] * inv;
            __nv_bfloat162 hh = __floats2bfloat162_rn(y0, y1);
            __nv_bfloat162 ll = __floats2bfloat162_rn(
                y0 - __bfloat162float(hh.x), y1 - __bfloat162float(hh.y));
            __nv_bfloat16* base = A3 + r * GEMM_K + col;
            *(__nv_bfloat162*)(base)        = hh;
            *(__nv_bfloat162*)(base + 1024) = hh;
            *(__nv_bfloat162*)(base + 2048) = ll;
        }
    }
}

// ============================================================
// Host launcher
// ============================================================
extern "C" void kernel_launch(void* const* d_in, const int* in_sizes, int n_in,
                              void* d_out, int out_size)
{
    (void)in_sizes; (void)n_in; (void)out_size;
    const float* x  = (const float*)d_in[0];
    const float* Wq = (const float*)d_in[1];
    const float* bq = (const float*)d_in[2];
    const float* Wk = (const float*)d_in[3];
    const float* bk = (const float*)d_in[4];
    const float* Wv = (const float*)d_in[5];
    const float* bv = (const float*)d_in[6];
    const float* Wo = (const float*)d_in[7];
    const float* bo = (const float*)d_in[8];
    float* out = (float*)d_out;

    __nv_bfloat16 *A3p, *B3fp, *B3op, *Qh, *Ql, *Kh, *Kl, *Vh, *Vl;
    cudaGetSymbolAddress((void**)&A3p, g_A3);
    cudaGetSymbolAddress((void**)&B3fp, g_B3f);
    cudaGetSymbolAddress((void**)&B3op, g_B3o);
    cudaGetSymbolAddress((void**)&Qh, g_Qhi);
    cudaGetSymbolAddress((void**)&Ql, g_Qlo);
    cudaGetSymbolAddress((void**)&Kh, g_Khi);
    cudaGetSymbolAddress((void**)&Kl, g_Klo);
    cudaGetSymbolAddress((void**)&Vh, g_Vhi);
    cudaGetSymbolAddress((void**)&Vl, g_Vlo);

    cudaFuncSetAttribute(gemm_hmma_kernel,
                         cudaFuncAttributeMaxDynamicSharedMemorySize,
                         G_SMEM_BYTES);

    const int nsp = (MM * EE / 4 + 255) / 256;
    const int nsb = (EE * EE / 4 + 255) / 256;
    split_a3_kernel<<<nsp, 256>>>(x, A3p);
    split_b3_kernel<<<nsb, 256>>>(Wq, B3fp, 3072, 0);
    split_b3_kernel<<<nsb, 256>>>(Wk, B3fp, 3072, 1024);
    split_b3_kernel<<<nsb, 256>>>(Wv, B3fp, 3072, 2048);
    split_b3_kernel<<<nsb, 256>>>(Wo, B3op, 1024, 0);

    // fused QKV GEMM: N = 3072
    dim3 gq(3072 / 128, MM / 128);   // (24, 32)
    gemm_hmma_kernel<<<gq, 128, G_SMEM_BYTES>>>(
        A3p, B3fp, 3072, bq, bk, bv, SCALE, nullptr,
        Qh, Ql, Kh, Kl, Vh, Vl);

    dim3 ga(SS / 64, HH, BB);        // (32, 16, 2)
    attn_mma_kernel<<<ga, 128>>>(Qh, Ql, Kh, Kl, Vh, Vl, A3p);

    // O projection: N = 1024, fp32 out
    dim3 go(1024 / 128, MM / 128);   // (8, 32)
    gemm_hmma_kernel<<<go, 128, G_SMEM_BYTES>>>(
        A3p, B3op, 1024, bo, bo, bo, 1.0f, out,
        nullptr, nullptr, nullptr, nullptr, nullptr, nullptr);
}

// round 8
// speedup vs baseline: 4.5539x; 1.4831x over previous
#include <cuda_runtime.h>
#include <cuda_fp16.h>
#include <math.h>
#include <stdint.h>

// Problem constants
#define BB 2
#define SS 2048
#define EE 1024
#define HH 16
#define DD 64
#define MM (BB * SS)
#define SCALE 0.03125f        // 1/sqrt(1024)

#define GEMM_K 2048           // 2*EE (fp16x2 emulation folded into K)

// -------- scratch (static device globals) --------
__device__ __half g_A2[(size_t)MM * GEMM_K];          // [M, 2K] (hi|lo)
__device__ __half g_B2f[(size_t)EE * 3072];           // QKV fused: [1024, 3072] (hi only)
__device__ __half g_B2o[(size_t)EE * 1024];           // O proj:   [1024, 1024] (hi only)
__device__ __half g_Qh[MM * EE], g_Ql[MM * EE];
__device__ __half g_Kh[MM * EE];
__device__ __half g_Vh[MM * EE];

__device__ __forceinline__ uint32_t sptr(const void* p) {
    return (uint32_t)__cvta_generic_to_shared(p);
}

#define LDSM_X4(r0, r1, r2, r3, addr)                                                   \
    asm volatile("ldmatrix.sync.aligned.m8n8.x4.shared.b16 {%0,%1,%2,%3}, [%4];"        \
        : "=r"(r0), "=r"(r1), "=r"(r2), "=r"(r3) : "r"(addr))
#define LDSM_X4_T(r0, r1, r2, r3, addr)                                                 \
    asm volatile("ldmatrix.sync.aligned.m8n8.x4.trans.shared.b16 {%0,%1,%2,%3}, [%4];"  \
        : "=r"(r0), "=r"(r1), "=r"(r2), "=r"(r3) : "r"(addr))
#define MMAF16(d, a, b0, b1)                                                            \
    asm volatile("mma.sync.aligned.m16n8k16.row.col.f32.f16.f16.f32 "                   \
        "{%0,%1,%2,%3}, {%4,%5,%6,%7}, {%8,%9}, {%0,%1,%2,%3};"                         \
        : "+f"((d)[0]), "+f"((d)[1]), "+f"((d)[2]), "+f"((d)[3])                        \
        : "r"((a)[0]), "r"((a)[1]), "r"((a)[2]), "r"((a)[3]), "r"(b0), "r"(b1))

__device__ __forceinline__ uint32_t packh(float a, float b) {
    __half2 h = __floats2half2_rn(a, b);
    return *(uint32_t*)&h;
}

// ============================================================
// Split kernels
// ============================================================
// x fp32 [M,1024] -> A2 [M,2048]: hi at k, lo at k+1024
__global__ void split_a2_kernel(const float* __restrict__ X,
                                __half* __restrict__ A2)
{
    int idx = blockIdx.x * 256 + threadIdx.x;     // over MM*EE/4
    if (idx >= MM * EE / 4) return;
    int i4 = idx * 4;
    int r = i4 >> 10, k = i4 & 1023;
    float4 x = *(const float4*)(X + i4);
    __half2 h0 = __floats2half2_rn(x.x, x.y);
    __half2 h1 = __floats2half2_rn(x.z, x.w);
    __half2 l0 = __floats2half2_rn(x.x - __half2float(h0.x),
                                   x.y - __half2float(h0.y));
    __half2 l1 = __floats2half2_rn(x.z - __half2float(h1.x),
                                   x.w - __half2float(h1.y));
    __half* p = A2 + (size_t)r * GEMM_K + k;
    *(__half2*)(p)          = h0;
    *(__half2*)(p + 2)      = h1;
    *(__half2*)(p + 1024)   = l0;
    *(__half2*)(p + 1026)   = l1;
}

// W[1024,1024] fp32 -> B2 (hi only) at column offset coff
__global__ void split_b2_kernel(const float* __restrict__ W,
                                __half* __restrict__ B2,
                                int ldn, int coff)
{
    int idx = blockIdx.x * 256 + threadIdx.x;     // over 1024*1024/4
    if (idx >= EE * EE / 4) return;
    int i4 = idx * 4;
    int k = i4 >> 10, n = i4 & 1023;
    float4 w = *(const float4*)(W + i4);
    __half* p = B2 + (size_t)k * ldn + coff + n;
    *(__half2*)(p)     = __floats2half2_rn(w.x, w.y);
    *(__half2*)(p + 2) = __floats2half2_rn(w.z, w.w);
}

// ============================================================
// fp16x2 GEMM (HMMA m16n8k16), fp32 accumulate.
// CTA tile 128x128, 128 threads (4 warps, 64x64/warp), BK=32,
// 3-stage cp.async. B rows repeat with period 1024 (&1023).
// Segment-aware epilogue (QKV fused).
// ============================================================
#define AST 40     // A smem row stride (half)
#define BST 136    // B smem row stride (half)
#define A_SBYTES (128 * AST * 2)
#define B_SBYTES (32 * BST * 2)
#define STAGE_BYTES (A_SBYTES + B_SBYTES)
#define G_SMEM_BYTES (3 * STAGE_BYTES)

__global__ __launch_bounds__(128, 2) void gemm_hmma_kernel(
    const __half* __restrict__ A,
    const __half* __restrict__ B, int ldb,
    const float* __restrict__ bias0, const float* __restrict__ bias1,
    const float* __restrict__ bias2, float scale0,
    float* __restrict__ Cf,
    __half* __restrict__ H0, __half* __restrict__ L0,
    __half* __restrict__ H1,
    __half* __restrict__ H2)
{
    extern __shared__ __align__(16) char dsm[];

    const int tid  = threadIdx.x;
    const int lane = tid & 31;
    const int warp = tid >> 5;
    const int bm = blockIdx.y * 128;
    const int bn = blockIdx.x * 128;
    const int wm = (warp >> 1) * 64;
    const int wn = (warp & 1) * 64;

    float acc[4][8][4];
    #pragma unroll
    for (int i = 0; i < 4; i++)
        #pragma unroll
        for (int j = 0; j < 8; j++)
            #pragma unroll
            for (int k = 0; k < 4; k++) acc[i][j][k] = 0.f;

    auto As = [&](int s) { return (__half*)(dsm + s * STAGE_BYTES); };
    auto Bs = [&](int s) { return (__half*)(dsm + s * STAGE_BYTES + A_SBYTES); };

    auto gload = [&](int s, int it) {
        const int k0 = it * 32;
        __half* as = As(s);
        __half* bs = Bs(s);
        #pragma unroll
        for (int i = 0; i < 4; i++) {
            int c = tid + i * 128;
            int r = c >> 2, kk = (c & 3) * 8;
            asm volatile("cp.async.cg.shared.global [%0], [%1], 16;" ::
                "r"(sptr(as + r * AST + kk)),
                "l"(A + (size_t)(bm + r) * GEMM_K + k0 + kk));
        }
        #pragma unroll
        for (int i = 0; i < 4; i++) {
            int c = tid + i * 128;
            int r = c >> 4, nn = (c & 15) * 8;
            asm volatile("cp.async.cg.shared.global [%0], [%1], 16;" ::
                "r"(sptr(bs + r * BST + nn)),
                "l"(B + (size_t)((k0 + r) & 1023) * ldb + bn + nn));
        }
        asm volatile("cp.async.commit_group;" ::: "memory");
    };

    constexpr int NSTEPS = GEMM_K / 32;  // 64
    gload(0, 0);
    gload(1, 1);

    for (int it = 0; it < NSTEPS; it++) {
        const int buf = it % 3;
        if (it + 2 < NSTEPS) {
            gload((it + 2) % 3, it + 2);
            asm volatile("cp.async.wait_group 2;" ::: "memory");
        } else if (it + 1 < NSTEPS) {
            asm volatile("cp.async.wait_group 1;" ::: "memory");
        } else {
            asm volatile("cp.async.wait_group 0;" ::: "memory");
        }
        __syncthreads();

        __half* as = As(buf);
        __half* bs = Bs(buf);
        #pragma unroll
        for (int ks = 0; ks < 2; ks++) {
            const int k0 = ks * 16;
            uint32_t af[4][4];
            #pragma unroll
            for (int mi = 0; mi < 4; mi++) {
                uint32_t addr = sptr(as + (wm + mi * 16 + (lane & 15)) * AST
                                        + k0 + (lane >> 4) * 8);
                LDSM_X4(af[mi][0], af[mi][1], af[mi][2], af[mi][3], addr);
            }
            uint32_t bf0[8], bf1[8];
            #pragma unroll
            for (int g = 0; g < 4; g++) {
                uint32_t addr = sptr(bs + (k0 + (lane & 15)) * BST
                                        + wn + g * 16 + (lane >> 4) * 8);
                uint32_t r0, r1, r2, r3;
                LDSM_X4_T(r0, r1, r2, r3, addr);
                bf0[2 * g]     = r0;  bf1[2 * g]     = r1;
                bf0[2 * g + 1] = r2;  bf1[2 * g + 1] = r3;
            }
            #pragma unroll
            for (int mi = 0; mi < 4; mi++)
                #pragma unroll
                for (int ni = 0; ni < 8; ni++)
                    MMAF16(acc[mi][ni], af[mi], bf0[ni], bf1[ni]);
        }
        __syncthreads();
    }

    // ---- segment-aware epilogue
    const int seg = bn >> 10;                    // 0=Q (or O-proj), 1=K, 2=V
    const float* bias = (seg == 0) ? bias0 : (seg == 1) ? bias1 : bias2;
    const float scale = (seg == 0) ? scale0 : 1.0f;
    __half* Hc = (seg == 0) ? H0 : (seg == 1) ? H1 : H2;
    const int lbn = bn & 1023;

    const int row_base = bm + wm + (lane >> 2);
    const int col_base = wn + (lane & 3) * 2;
    #pragma unroll
    for (int ni = 0; ni < 8; ni++) {
        int col = lbn + col_base + ni * 8;
        float b0 = bias[col], b1 = bias[col + 1];
        #pragma unroll
        for (int mi = 0; mi < 4; mi++) {
            #pragma unroll
            for (int half = 0; half < 2; half++) {
                int r = row_base + mi * 16 + half * 8;
                float y0 = acc[mi][ni][2 * half]     + b0;
                float y1 = acc[mi][ni][2 * half + 1] + b1;
                if (Cf) {
                    *(float2*)&Cf[(size_t)r * EE + col] = make_float2(y0, y1);
                } else {
                    y0 *= scale; y1 *= scale;
                    __half2 hh = __floats2half2_rn(y0, y1);
                    *(__half2*)&Hc[(size_t)r * EE + col] = hh;
                    if (seg == 0) {
                        __half2 ll = __floats2half2_rn(
                            y0 - __half2float(hh.x), y1 - __half2float(hh.y));
                        *(__half2*)&L0[(size_t)r * EE + col] = ll;
                    }
                }
            }
        }
    }
}

// ============================================================
// Tensor-core flash attention (causal), fp16x2 split precision.
// S = (qh+ql)*kh ; O = (ph+pl)*vh. K/V need hi only.
// Writes o-proj A2 operand (hi|lo) directly.
// ============================================================
#define KVS 72

__global__ __launch_bounds__(128) void attn_mma_kernel(
    const __half* __restrict__ Qhi, const __half* __restrict__ Qlo,
    const __half* __restrict__ Khi, const __half* __restrict__ Vhi,
    __half* __restrict__ A2)
{
    __shared__ __align__(16) __half sK[64 * KVS];
    __shared__ __align__(16) __half sV[64 * KVS];

    const int tid  = threadIdx.x;
    const int lane = tid & 31;
    const int warp = tid >> 5;
    const int qt = gridDim.x - 1 - blockIdx.x;   // heavy tiles first
    const int h  = blockIdx.y;
    const int b  = blockIdx.z;
    const size_t tok0 = (size_t)b * SS + qt * 64;
    const int hcol = h * 64;

    // stage Q: hi via sK, lo via sV
    #pragma unroll
    for (int i = 0; i < 4; i++) {
        int idx = tid + i * 128;
        int r = idx >> 3, c = (idx & 7) * 8;
        *(uint4*)(sK + r * KVS + c) = *(const uint4*)(Qhi + (tok0 + r) * EE + hcol + c);
        *(uint4*)(sV + r * KVS + c) = *(const uint4*)(Qlo + (tok0 + r) * EE + hcol + c);
    }
    __syncthreads();

    uint32_t qh[4][4], ql[4][4];
    {
        int r = warp * 16 + (lane & 15);
        #pragma unroll
        for (int kt = 0; kt < 4; kt++) {
            int c = kt * 16 + (lane >> 4) * 8;
            LDSM_X4(qh[kt][0], qh[kt][1], qh[kt][2], qh[kt][3], sptr(sK + r * KVS + c));
            LDSM_X4(ql[kt][0], ql[kt][1], ql[kt][2], ql[kt][3], sptr(sV + r * KVS + c));
        }
    }

    float o[8][4];
    #pragma unroll
    for (int ni = 0; ni < 8; ni++)
        #pragma unroll
        for (int j = 0; j < 4; j++) o[ni][j] = 0.f;
    float m0 = -1e30f, m1 = -1e30f, l0 = 0.f, l1 = 0.f;
    const int r0loc = warp * 16 + (lane >> 2);

    for (int t = 0; t <= qt; t++) {
        __syncthreads();
        #pragma unroll
        for (int i = 0; i < 4; i++) {
            int idx = tid + i * 128;
            int r = idx >> 3, c = (idx & 7) * 8;
            size_t g = ((size_t)b * SS + t * 64 + r) * EE + hcol + c;
            *(uint4*)(sK + r * KVS + c) = *(const uint4*)(Khi + g);
            *(uint4*)(sV + r * KVS + c) = *(const uint4*)(Vhi + g);
        }
        __syncthreads();

        // ---- scores: S = (qh + ql) * kh
        float s[8][4];
        #pragma unroll
        for (int ni = 0; ni < 8; ni++)
            #pragma unroll
            for (int j = 0; j < 4; j++) s[ni][j] = 0.f;

        #pragma unroll
        for (int kt = 0; kt < 4; kt++) {
            uint32_t bh[8][2];
            #pragma unroll
            for (int g = 0; g < 4; g++) {
                int row = g * 16 + (lane & 7) + ((lane & 16) >> 1);
                int cx  = (kt * 2 + ((lane >> 3) & 1)) * 8;
                uint32_t r0, r1, r2, r3;
                LDSM_X4(r0, r1, r2, r3, sptr(sK + row * KVS + cx));
                bh[2 * g][0] = r0; bh[2 * g][1] = r1;
                bh[2 * g + 1][0] = r2; bh[2 * g + 1][1] = r3;
            }
            #pragma unroll
            for (int ni = 0; ni < 8; ni++) {
                MMAF16(s[ni], qh[kt], bh[ni][0], bh[ni][1]);
                MMAF16(s[ni], ql[kt], bh[ni][0], bh[ni][1]);
            }
        }

        if (t == qt) {
            #pragma unroll
            for (int ni = 0; ni < 8; ni++) {
                int c0 = ni * 8 + 2 * (lane & 3);
                if (c0     > r0loc)     s[ni][0] = -1e30f;
                if (c0 + 1 > r0loc)     s[ni][1] = -1e30f;
                if (c0     > r0loc + 8) s[ni][2] = -1e30f;
                if (c0 + 1 > r0loc + 8) s[ni][3] = -1e30f;
            }
        }

        float tm0 = -1e30f, tm1 = -1e30f;
        #pragma unroll
        for (int ni = 0; ni < 8; ni++) {
            tm0 = fmaxf(tm0, fmaxf(s[ni][0], s[ni][1]));
            tm1 = fmaxf(tm1, fmaxf(s[ni][2], s[ni][3]));
        }
        tm0 = fmaxf(tm0, __shfl_xor_sync(0xffffffffu, tm0, 1));
        tm0 = fmaxf(tm0, __shfl_xor_sync(0xffffffffu, tm0, 2));
        tm1 = fmaxf(tm1, __shfl_xor_sync(0xffffffffu, tm1, 1));
        tm1 = fmaxf(tm1, __shfl_xor_sync(0xffffffffu, tm1, 2));
        float mn0 = fmaxf(m0, tm0), mn1 = fmaxf(m1, tm1);
        float cf0 = __expf(m0 - mn0), cf1 = __expf(m1 - mn1);
        l0 *= cf0; l1 *= cf1;
        #pragma unroll
        for (int ni = 0; ni < 8; ni++) {
            o[ni][0] *= cf0; o[ni][1] *= cf0;
            o[ni][2] *= cf1; o[ni][3] *= cf1;
        }
        #pragma unroll
        for (int ni = 0; ni < 8; ni++) {
            s[ni][0] = __expf(s[ni][0] - mn0);
            s[ni][1] = __expf(s[ni][1] - mn0);
            s[ni][2] = __expf(s[ni][2] - mn1);
            s[ni][3] = __expf(s[ni][3] - mn1);
            l0 += s[ni][0] + s[ni][1];
            l1 += s[ni][2] + s[ni][3];
        }
        m0 = mn0; m1 = mn1;

        // ---- O += (ph + pl) * vh
        #pragma unroll
        for (int kt = 0; kt < 4; kt++) {
            uint32_t ah[4], al[4];
            {
                float f0 = s[2 * kt][0], f1 = s[2 * kt][1];
                float f2 = s[2 * kt][2], f3 = s[2 * kt][3];
                float g0 = s[2 * kt + 1][0], g1 = s[2 * kt + 1][1];
                float g2 = s[2 * kt + 1][2], g3 = s[2 * kt + 1][3];
                ah[0] = packh(f0, f1); ah[1] = packh(f2, f3);
                ah[2] = packh(g0, g1); ah[3] = packh(g2, g3);
                __half2 h2;
                h2 = *(__half2*)&ah[0];
                al[0] = packh(f0 - __half2float(h2.x), f1 - __half2float(h2.y));
                h2 = *(__half2*)&ah[1];
                al[1] = packh(f2 - __half2float(h2.x), f3 - __half2float(h2.y));
                h2 = *(__half2*)&ah[2];
                al[2] = packh(g0 - __half2float(h2.x), g1 - __half2float(h2.y));
                h2 = *(__half2*)&ah[3];
                al[3] = packh(g2 - __half2float(h2.x), g3 - __half2float(h2.y));
            }
            uint32_t vh[8][2];
            #pragma unroll
            for (int g = 0; g < 4; g++) {
                int row = kt * 16 + (lane & 15);
                int cx  = (g * 2 + (lane >> 4)) * 8;
                uint32_t r0, r1, r2, r3;
                LDSM_X4_T(r0, r1, r2, r3, sptr(sV + row * KVS + cx));
                vh[2 * g][0] = r0; vh[2 * g][1] = r1;
                vh[2 * g + 1][0] = r2; vh[2 * g + 1][1] = r3;
            }
            #pragma unroll
            for (int ni = 0; ni < 8; ni++) {
                MMAF16(o[ni], ah, vh[ni][0], vh[ni][1]);
                MMAF16(o[ni], al, vh[ni][0], vh[ni][1]);
            }
        }
    }

    l0 += __shfl_xor_sync(0xffffffffu, l0, 1);
    l0 += __shfl_xor_sync(0xffffffffu, l0, 2);
    l1 += __shfl_xor_sync(0xffffffffu, l1, 1);
    l1 += __shfl_xor_sync(0xffffffffu, l1, 2);
    float i0 = 1.f / l0, i1 = 1.f / l1;

    size_t row0 = tok0 + warp * 16 + (lane >> 2);
    size_t row1 = row0 + 8;
    #pragma unroll
    for (int ni = 0; ni < 8; ni++) {
        int col = hcol + ni * 8 + 2 * (lane & 3);
        #pragma unroll
        for (int half = 0; half < 2; half++) {
            size_t r = half ? row1 : row0;
            float inv = half ? i1 : i0;
            float y0 = o[ni][2 * half] * inv, y1 = o[ni][2 * half + 1] * inv;
            __half2 hh = __floats2half2_rn(y0, y1);
            __half2 ll = __floats2half2_rn(
                y0 - __half2float(hh.x), y1 - __half2float(hh.y));
            __half* base = A2 + r * GEMM_K + col;
            *(__half2*)(base)        = hh;
            *(__half2*)(base + 1024) = ll;
        }
    }
}

// ============================================================
// Host launcher
// ============================================================
extern "C" void kernel_launch(void* const* d_in, const int* in_sizes, int n_in,
                              void* d_out, int out_size)
{
    (void)in_sizes; (void)n_in; (void)out_size;
    const float* x  = (const float*)d_in[0];
    const float* Wq = (const float*)d_in[1];
    const float* bq = (const float*)d_in[2];
    const float* Wk = (const float*)d_in[3];
    const float* bk = (const float*)d_in[4];
    const float* Wv = (const float*)d_in[5];
    const float* bv = (const float*)d_in[6];
    const float* Wo = (const float*)d_in[7];
    const float* bo = (const float*)d_in[8];
    float* out = (float*)d_out;

    __half *A2p, *B2fp, *B2op, *Qh, *Ql, *Kh, *Vh;
    cudaGetSymbolAddress((void**)&A2p, g_A2);
    cudaGetSymbolAddress((void**)&B2fp, g_B2f);
    cudaGetSymbolAddress((void**)&B2op, g_B2o);
    cudaGetSymbolAddress((void**)&Qh, g_Qh);
    cudaGetSymbolAddress((void**)&Ql, g_Ql);
    cudaGetSymbolAddress((void**)&Kh, g_Kh);
    cudaGetSymbolAddress((void**)&Vh, g_Vh);

    cudaFuncSetAttribute(gemm_hmma_kernel,
                         cudaFuncAttributeMaxDynamicSharedMemorySize,
                         G_SMEM_BYTES);

    const int nsp = (MM * EE / 4 + 255) / 256;
    const int nsb = (EE * EE / 4 + 255) / 256;
    split_a2_kernel<<<nsp, 256>>>(x, A2p);
    split_b2_kernel<<<nsb, 256>>>(Wq, B2fp, 3072, 0);
    split_b2_kernel<<<nsb, 256>>>(Wk, B2fp, 3072, 1024);
    split_b2_kernel<<<nsb, 256>>>(Wv, B2fp, 3072, 2048);
    split_b2_kernel<<<nsb, 256>>>(Wo, B2op, 1024, 0);

    // fused QKV GEMM: N = 3072
    dim3 gq(3072 / 128, MM / 128);   // (24, 32)
    gemm_hmma_kernel<<<gq, 128, G_SMEM_BYTES>>>(
        A2p, B2fp, 3072, bq, bk, bv, SCALE, nullptr,
        Qh, Ql, Kh, Vh);

    dim3 ga(SS / 64, HH, BB);        // (32, 16, 2)
    attn_mma_kernel<<<ga, 128>>>(Qh, Ql, Kh, Vh, A2p);

    // O projection: N = 1024, fp32 out
    dim3 go(1024 / 128, MM / 128);   // (8, 32)
    gemm_hmma_kernel<<<go, 128, G_SMEM_BYTES>>>(
        A2p, B2op, 1024, bo, bo, bo, 1.0f, out,
        nullptr, nullptr, nullptr, nullptr);
}